// round 1
// baseline (speedup 1.0000x reference)
#include <cuda_runtime.h>

// StructNDeconv2D: depthwise conv_transpose2d (K=3, stride=2, pad=1) normalized
// convolution. Key identity: OH = 2*H-1 = 511 means every tap is always in
// bounds, and parity of (oy, ox) selects which of the 9 softplus-weights apply:
//   even oy -> ky=1 only; odd oy -> ky in {0,2}. Same in x.
// So each output pixel is a branchless 4-tap gather; cdenom (deconv of ones)
// is just the sum of the active weights.

#define EPS_F 1e-20f

__device__ float g_sw[32 * 9];  // softplus(spatial_weight), per channel

__global__ void softplus_prep_kernel(const float* __restrict__ w) {
    int i = threadIdx.x;
    if (i < 32 * 9) {
        float x = w[i];
        // logaddexp(x, 0) = max(x,0) + log1p(exp(-|x|))
        g_sw[i] = fmaxf(x, 0.0f) + log1pf(expf(-fabsf(x)));
    }
}

__global__ __launch_bounds__(256) void deconv_norm_kernel(
    const float* __restrict__ d,
    const float* __restrict__ cd,
    const float* __restrict__ bias,
    float* __restrict__ out)
{
    constexpr int H = 256, W = 256, OH = 511, OW = 511;
    constexpr int BC = 256;  // B*C = 8*32

    int ox = blockIdx.x * blockDim.x + threadIdx.x;
    if (ox >= OW) return;
    int oy = blockIdx.y;
    int bc = blockIdx.z;
    int c  = bc & 31;

    const float* Wc = g_sw + c * 9;

    int py = oy & 1;
    int px = ox & 1;

    // Input coordinates (always in [0, 255]):
    //  r0 pairs with ky = (py ? 0 : 1); r1 pairs with ky = 2 (only if py)
    int r0 = (oy + 1) >> 1;
    int r1 = oy >> 1;
    int i0 = (ox + 1) >> 1;
    int i1 = ox >> 1;

    // Effective (softplus'd) weights per parity class. Zero-weight taps have
    // coinciding addresses with live taps, so they cost no extra traffic.
    int kyA = py ? 0 : 3;            // row offset into Wc (ky=0 or ky=1)
    int kxA = px ? 0 : 1;            // col offset       (kx=0 or kx=1)
    float c00 = Wc[kyA + kxA];
    float c01 = px        ? Wc[kyA + 2]  : 0.0f;
    float c10 = py        ? Wc[6 + kxA]  : 0.0f;
    float c11 = (py & px) ? Wc[8]        : 0.0f;

    size_t plane = (size_t)bc * (H * W);
    const float* dp = d  + plane;
    const float* cp = cd + plane;

    int o00 = r0 * W + i0;
    int o01 = r0 * W + i1;
    int o10 = r1 * W + i0;
    int o11 = r1 * W + i1;

    float cd00 = cp[o00], cd01 = cp[o01], cd10 = cp[o10], cd11 = cp[o11];
    float d00  = dp[o00], d01  = dp[o01], d10  = dp[o10], d11  = dp[o11];

    float den  = c00 * cd00 + c01 * cd01 + c10 * cd10 + c11 * cd11;
    float nom  = c00 * cd00 * d00 + c01 * cd01 * d01
               + c10 * cd10 * d10 + c11 * cd11 * d11;
    float cden = c00 + c01 + c10 + c11;   // deconv(ones) at this pixel

    float dout  = __fdividef(nom, den + EPS_F) + __ldg(bias + c);
    float cdout = __fdividef(den, cden + EPS_F);

    size_t N    = (size_t)BC * OH * OW;
    size_t oidx = ((size_t)bc * OH + oy) * OW + ox;
    out[oidx]     = dout;
    out[N + oidx] = cdout;
}

extern "C" void kernel_launch(void* const* d_in, const int* in_sizes, int n_in,
                              void* d_out, int out_size) {
    const float* d    = (const float*)d_in[0];
    const float* cd   = (const float*)d_in[1];
    const float* sw   = (const float*)d_in[2];
    const float* bias = (const float*)d_in[3];
    float* out = (float*)d_out;

    softplus_prep_kernel<<<1, 288>>>(sw);

    dim3 block(256);
    dim3 grid((511 + 255) / 256, 511, 256);  // (2, OH, B*C)
    deconv_norm_kernel<<<grid, block>>>(d, cd, bias, out);
}

// round 2
// speedup vs baseline: 1.5945x; 1.5945x over previous
#include <cuda_runtime.h>

// StructNDeconv2D: depthwise conv_transpose2d (K=3, stride=2, pad=1) normalized
// convolution, OH = 2H-1 = 511 so every tap is in bounds.
//
// Round-2 structure: one thread produces the 2x2 output parity block at
// (2y, 2x)..(2y+1, 2x+1) from the four inputs (y..y+1, x..x+1):
//   (2y,   2x  ): w4@(y,x)
//   (2y,   2x+1): w3@(y,x+1) + w5@(y,x)
//   (2y+1, 2x  ): w1@(y+1,x) + w7@(y,x)
//   (2y+1, 2x+1): w0@(y+1,x+1) + w2@(y+1,x) + w6@(y,x+1) + w8@(y,x)
// cdenom (deconv of ones) per parity class is a constant per channel; its
// reciprocal is precomputed so cd_out is a single multiply.

#define EPS_F 1e-20f

// Per-channel packed params: [0..8]=softplus(w), [9..12]=1/(cden+eps) for
// ee/eo/oe/oo parity classes, [13]=bias, [14..15]=pad. 64B aligned -> 4x LDG.128.
__device__ __align__(16) float g_wp[32][16];

__global__ void prep_kernel(const float* __restrict__ w,
                            const float* __restrict__ bias) {
    int c = threadIdx.x;
    if (c >= 32) return;
    float s[9];
#pragma unroll
    for (int i = 0; i < 9; i++) {
        float x = w[c * 9 + i];
        // softplus = max(x,0) + log1p(exp(-|x|))
        s[i] = fmaxf(x, 0.0f) + log1pf(expf(-fabsf(x)));
        g_wp[c][i] = s[i];
    }
    g_wp[c][9]  = 1.0f / (s[4] + EPS_F);                      // ee
    g_wp[c][10] = 1.0f / (s[3] + s[5] + EPS_F);               // eo
    g_wp[c][11] = 1.0f / (s[1] + s[7] + EPS_F);               // oe
    g_wp[c][12] = 1.0f / (s[0] + s[2] + s[6] + s[8] + EPS_F); // oo
    g_wp[c][13] = bias[c];
    g_wp[c][14] = 0.0f;
    g_wp[c][15] = 0.0f;
}

__global__ __launch_bounds__(256) void deconv2x2_kernel(
    const float* __restrict__ d,
    const float* __restrict__ cd,
    float* __restrict__ out)
{
    constexpr int H = 256, W = 256, OH = 511, OW = 511;

    int x  = blockIdx.x * 64 + threadIdx.x;   // input col,  [0,255]
    int y  = blockIdx.y * 4  + threadIdx.y;   // input row,  [0,255]
    int bc = blockIdx.z;                      // B*C plane,  [0,255]
    int c  = bc & 31;

    // Channel constants: 4 vector loads (L1 broadcast hits within block).
    const float4* wp = reinterpret_cast<const float4*>(g_wp[c]);
    float4 w0 = wp[0], w1 = wp[1], w2 = wp[2], w3 = wp[3];
    float s0 = w0.x, s1 = w0.y, s2 = w0.z, s3 = w0.w;
    float s4 = w1.x, s5 = w1.y, s6 = w1.z, s7 = w1.w;
    float s8 = w2.x, ree = w2.y, reo = w2.z, roe = w2.w;
    float roo = w3.x, b = w3.y;

    bool xe = (x < W - 1);       // column 2x+1 exists (x < 255)
    bool ye = (y < H - 1);       // row 2y+1 exists
    int x1 = xe ? x + 1 : x;     // clamped: edge value unused but load is safe
    int y1 = ye ? y + 1 : y;

    size_t plane = (size_t)bc * (H * W);
    const float* dp = d  + plane;
    const float* cp = cd + plane;

    int i00 = y  * W + x;
    int i01 = y  * W + x1;
    int i10 = y1 * W + x;
    int i11 = y1 * W + x1;

    float cd00 = cp[i00], cd01 = cp[i01], cd10 = cp[i10], cd11 = cp[i11];
    float d00  = dp[i00], d01  = dp[i01], d10  = dp[i10], d11  = dp[i11];

    // (2y, 2x): center tap only
    float den_ee  = s4 * cd00;
    float dout_ee = __fdividef(den_ee * d00, den_ee + EPS_F) + b;
    float cdo_ee  = den_ee * ree;

    // (2y, 2x+1)
    float a_eo = s3 * cd01, b_eo = s5 * cd00;
    float den_eo  = a_eo + b_eo;
    float dout_eo = __fdividef(fmaf(a_eo, d01, b_eo * d00), den_eo + EPS_F) + b;
    float cdo_eo  = den_eo * reo;

    // (2y+1, 2x)
    float a_oe = s1 * cd10, b_oe = s7 * cd00;
    float den_oe  = a_oe + b_oe;
    float dout_oe = __fdividef(fmaf(a_oe, d10, b_oe * d00), den_oe + EPS_F) + b;
    float cdo_oe  = den_oe * roe;

    // (2y+1, 2x+1)
    float t0 = s0 * cd11, t2 = s2 * cd10, t6 = s6 * cd01, t8 = s8 * cd00;
    float den_oo  = (t0 + t2) + (t6 + t8);
    float nom_oo  = fmaf(t0, d11, fmaf(t2, d10, fmaf(t6, d01, t8 * d00)));
    float dout_oo = __fdividef(nom_oo, den_oo + EPS_F) + b;
    float cdo_oo  = den_oo * roo;

    size_t N    = (size_t)256 * OH * OW;
    size_t rowE = ((size_t)bc * OH + 2 * y) * OW + 2 * x;
    float* oE = out + rowE;

    oE[0]     = dout_ee;
    oE[N]     = cdo_ee;
    if (xe) {
        oE[1]     = dout_eo;
        oE[N + 1] = cdo_eo;
    }
    if (ye) {
        float* oO = oE + OW;
        oO[0]     = dout_oe;
        oO[N]     = cdo_oe;
        if (xe) {
            oO[1]     = dout_oo;
            oO[N + 1] = cdo_oo;
        }
    }
}

extern "C" void kernel_launch(void* const* d_in, const int* in_sizes, int n_in,
                              void* d_out, int out_size) {
    const float* d    = (const float*)d_in[0];
    const float* cd   = (const float*)d_in[1];
    const float* sw   = (const float*)d_in[2];
    const float* bias = (const float*)d_in[3];
    float* out = (float*)d_out;

    prep_kernel<<<1, 32>>>(sw, bias);

    dim3 block(64, 4);
    dim3 grid(256 / 64, 256 / 4, 256);  // (4, 64, 256)
    deconv2x2_kernel<<<grid, block>>>(d, cd, out);
}

// round 3
// speedup vs baseline: 1.7883x; 1.1215x over previous
#include <cuda_runtime.h>

// StructNDeconv2D: depthwise conv_transpose2d (K=3, stride=2, pad=1) normalized
// convolution, OH = 2H-1 = 511 so every tap is in bounds.
//
// One thread handles 4 input rows x 1 input col-pair -> an 8x2 output patch.
// All 20 input loads are front-batched for MLP; 4 unrolled iterations emit
// the 2x2 output parity blocks. cdenom (deconv of ones) per parity class is a
// per-channel constant; its reciprocal is precomputed.

#define EPS_F 1e-20f

// Per-channel packed params: [0..8]=softplus(w), [9..12]=1/(cden+eps) for
// ee/eo/oe/oo parity classes, [13]=bias. 64B aligned -> 4x LDG.128.
__device__ __align__(16) float g_wp[32][16];

__global__ void prep_kernel(const float* __restrict__ w,
                            const float* __restrict__ bias) {
    int c = threadIdx.x;
    if (c >= 32) return;
    float s[9];
#pragma unroll
    for (int i = 0; i < 9; i++) {
        float x = w[c * 9 + i];
        s[i] = fmaxf(x, 0.0f) + log1pf(expf(-fabsf(x)));  // softplus
        g_wp[c][i] = s[i];
    }
    g_wp[c][9]  = 1.0f / (s[4] + EPS_F);                      // ee
    g_wp[c][10] = 1.0f / (s[3] + s[5] + EPS_F);               // eo
    g_wp[c][11] = 1.0f / (s[1] + s[7] + EPS_F);               // oe
    g_wp[c][12] = 1.0f / (s[0] + s[2] + s[6] + s[8] + EPS_F); // oo
    g_wp[c][13] = bias[c];
    g_wp[c][14] = 0.0f;
    g_wp[c][15] = 0.0f;
}

__global__ __launch_bounds__(256) void deconv4r_kernel(
    const float* __restrict__ d,
    const float* __restrict__ cd,
    float* __restrict__ out)
{
    constexpr int H = 256, W = 256, OH = 511, OW = 511;
    constexpr int R = 4;  // input rows per thread

    int x  = blockIdx.x * 64 + threadIdx.x;          // input col [0,255]
    int y0 = (blockIdx.y * 4 + threadIdx.y) * R;     // first input row
    int bc = blockIdx.z;
    int c  = bc & 31;

    // Channel constants (4x LDG.128, L1-broadcast within the block).
    const float4* wp = reinterpret_cast<const float4*>(g_wp[c]);
    float4 w0 = wp[0], w1 = wp[1], w2 = wp[2], w3 = wp[3];
    float s0 = w0.x, s1 = w0.y, s2 = w0.z, s3 = w0.w;
    float s4 = w1.x, s5 = w1.y, s6 = w1.z, s7 = w1.w;
    float s8 = w2.x, ree = w2.y, reo = w2.z, roe = w2.w;
    float roo = w3.x, b = w3.y;

    bool xe = (x < W - 1);
    int  x1 = xe ? x + 1 : x;   // clamped; edge value never used but load safe

    size_t plane = (size_t)bc * (H * W);
    const float* dp = d  + plane;
    const float* cp = cd + plane;

    // Front-batched loads: rows y0..y0+R (R+1 rows), cols {x, x+1}.
    float cdA[R + 1], cdB[R + 1], dA[R + 1], dB[R + 1];
#pragma unroll
    for (int i = 0; i <= R; i++) {
        int ry = y0 + i;
        ry = ry > H - 1 ? H - 1 : ry;   // clamp (row 256 -> unused values)
        int o0 = ry * W + x;
        int o1 = ry * W + x1;
        cdA[i] = cp[o0];
        cdB[i] = cp[o1];
        dA[i]  = dp[o0];
        dB[i]  = dp[o1];
    }

    size_t N = (size_t)256 * OH * OW;

#pragma unroll
    for (int r = 0; r < R; r++) {
        int y = y0 + r;
        bool ye = (y < H - 1);

        float cd00 = cdA[r],     d00 = dA[r];
        float cd01 = cdB[r],     d01 = dB[r];
        float cd10 = cdA[r + 1], d10 = dA[r + 1];
        float cd11 = cdB[r + 1], d11 = dB[r + 1];

        // (2y, 2x): center tap only
        float den_ee  = s4 * cd00;
        float dout_ee = __fdividef(den_ee * d00, den_ee + EPS_F) + b;
        float cdo_ee  = den_ee * ree;

        // (2y, 2x+1)
        float a_eo = s3 * cd01, b_eo = s5 * cd00;
        float den_eo  = a_eo + b_eo;
        float dout_eo = __fdividef(fmaf(a_eo, d01, b_eo * d00), den_eo + EPS_F) + b;
        float cdo_eo  = den_eo * reo;

        // (2y+1, 2x)
        float a_oe = s1 * cd10, b_oe = s7 * cd00;
        float den_oe  = a_oe + b_oe;
        float dout_oe = __fdividef(fmaf(a_oe, d10, b_oe * d00), den_oe + EPS_F) + b;
        float cdo_oe  = den_oe * roe;

        // (2y+1, 2x+1)
        float t0 = s0 * cd11, t2 = s2 * cd10, t6 = s6 * cd01, t8 = s8 * cd00;
        float den_oo  = (t0 + t2) + (t6 + t8);
        float nom_oo  = fmaf(t0, d11, fmaf(t2, d10, fmaf(t6, d01, t8 * d00)));
        float dout_oo = __fdividef(nom_oo, den_oo + EPS_F) + b;
        float cdo_oo  = den_oo * roo;

        size_t rowE = ((size_t)bc * OH + 2 * y) * OW + 2 * x;
        float* oE = out + rowE;

        __stcs(oE,     dout_ee);
        __stcs(oE + N, cdo_ee);
        if (xe) {
            __stcs(oE + 1,     dout_eo);
            __stcs(oE + N + 1, cdo_eo);
        }
        if (ye) {
            float* oO = oE + OW;
            __stcs(oO,     dout_oe);
            __stcs(oO + N, cdo_oe);
            if (xe) {
                __stcs(oO + 1,     dout_oo);
                __stcs(oO + N + 1, cdo_oo);
            }
        }
    }
}

extern "C" void kernel_launch(void* const* d_in, const int* in_sizes, int n_in,
                              void* d_out, int out_size) {
    const float* d    = (const float*)d_in[0];
    const float* cd   = (const float*)d_in[1];
    const float* sw   = (const float*)d_in[2];
    const float* bias = (const float*)d_in[3];
    float* out = (float*)d_out;

    prep_kernel<<<1, 32>>>(sw, bias);

    dim3 block(64, 4);
    dim3 grid(256 / 64, 256 / (4 * 4), 256);  // (4, 16, 256)
    deconv4r_kernel<<<grid, block>>>(d, cd, out);
}

// round 4
// speedup vs baseline: 2.1686x; 1.2127x over previous
#include <cuda_runtime.h>

// StructNDeconv2D: depthwise conv_transpose2d (K=3, stride=2, pad=1) normalized
// convolution. OH = 2H-1 = 511 so every tap is in bounds.
//
// Round-4: thread owns input cols {X, X+1} (X even) and R=2 input rows ->
// 4x4 output patch per plane. Inputs via float2 loads (coalesced); outputs via
// parity-adaptive paired stores (row base parity is uniform per block since
// it equals (blockIdx.z + oy) & 1).

#define EPS_F 1e-20f

// Per-channel packed params: [0..8]=softplus(w), [9..12]=1/(cden+eps) for
// ee/eo/oe/oo parity classes, [13]=bias. 64B aligned -> 4x LDG.128.
__device__ __align__(16) float g_wp[32][16];

__global__ void prep_kernel(const float* __restrict__ w,
                            const float* __restrict__ bias) {
    int c = threadIdx.x;
    if (c >= 32) return;
    float s[9];
#pragma unroll
    for (int i = 0; i < 9; i++) {
        float x = w[c * 9 + i];
        s[i] = fmaxf(x, 0.0f) + log1pf(expf(-fabsf(x)));  // softplus
        g_wp[c][i] = s[i];
    }
    g_wp[c][9]  = 1.0f / (s[4] + EPS_F);                      // ee
    g_wp[c][10] = 1.0f / (s[3] + s[5] + EPS_F);               // eo
    g_wp[c][11] = 1.0f / (s[1] + s[7] + EPS_F);               // oe
    g_wp[c][12] = 1.0f / (s[0] + s[2] + s[6] + s[8] + EPS_F); // oo
    g_wp[c][13] = bias[c];
    g_wp[c][14] = 0.0f;
    g_wp[c][15] = 0.0f;
}

// Store 4 consecutive output floats at p (may be only 3 valid when !xe).
// aligned == (p is 8-byte aligned); uniform within a block.
__device__ __forceinline__ void store_row4(float* p, float a, float b,
                                           float c, float d,
                                           bool aligned, bool xe) {
    if (aligned) {
        __stcs(reinterpret_cast<float2*>(p), make_float2(a, b));
        if (xe) __stcs(reinterpret_cast<float2*>(p + 2), make_float2(c, d));
        else    __stcs(p + 2, c);
    } else {
        __stcs(p, a);
        __stcs(reinterpret_cast<float2*>(p + 1), make_float2(b, c));
        if (xe) __stcs(p + 3, d);
    }
}

// One 2x2 output parity block from the 2x2 input neighborhood.
__device__ __forceinline__ void block2x2(
    float cd00, float cd01, float cd10, float cd11,
    float d00,  float d01,  float d10,  float d11,
    float s0, float s1, float s2, float s3, float s4,
    float s5, float s6, float s7, float s8,
    float ree, float reo, float roe, float roo, float b,
    float& dee, float& deo, float& doe, float& doo,
    float& cee, float& ceo, float& coe, float& coo)
{
    float den_ee = s4 * cd00;
    dee = __fdividef(den_ee * d00, den_ee + EPS_F) + b;
    cee = den_ee * ree;

    float a_eo = s3 * cd01, b_eo = s5 * cd00;
    float den_eo = a_eo + b_eo;
    deo = __fdividef(fmaf(a_eo, d01, b_eo * d00), den_eo + EPS_F) + b;
    ceo = den_eo * reo;

    float a_oe = s1 * cd10, b_oe = s7 * cd00;
    float den_oe = a_oe + b_oe;
    doe = __fdividef(fmaf(a_oe, d10, b_oe * d00), den_oe + EPS_F) + b;
    coe = den_oe * roe;

    float t0 = s0 * cd11, t2 = s2 * cd10, t6 = s6 * cd01, t8 = s8 * cd00;
    float den_oo = (t0 + t2) + (t6 + t8);
    doo = __fdividef(fmaf(t0, d11, fmaf(t2, d10, fmaf(t6, d01, t8 * d00))),
                     den_oo + EPS_F) + b;
    coo = den_oo * roo;
}

__global__ __launch_bounds__(256) void deconv_v4_kernel(
    const float* __restrict__ d,
    const float* __restrict__ cd,
    float* __restrict__ out)
{
    constexpr int H = 256, W = 256, OH = 511, OW = 511;
    constexpr int R = 2;  // input rows per thread

    int xt = blockIdx.x * 64 + threadIdx.x;        // col-pair index [0,128)
    int X  = xt * 2;                               // first owned input col
    int y0 = (blockIdx.y * 4 + threadIdx.y) * R;   // first input row
    int bc = blockIdx.z;
    int c  = bc & 31;

    const float4* wp = reinterpret_cast<const float4*>(g_wp[c]);
    float4 w0 = wp[0], w1 = wp[1], w2 = wp[2], w3 = wp[3];
    float s0 = w0.x, s1 = w0.y, s2 = w0.z, s3 = w0.w;
    float s4 = w1.x, s5 = w1.y, s6 = w1.z, s7 = w1.w;
    float s8 = w2.x, ree = w2.y, reo = w2.z, roe = w2.w;
    float roo = w3.x, b = w3.y;

    bool xe = (xt < 127);            // output col 4xt+3 exists
    int  x2 = xe ? X + 2 : X + 1;    // clamped; value unused when !xe

    size_t plane = (size_t)bc * (H * W);
    const float* dp = d  + plane;
    const float* cp = cd + plane;

    // Front-batched loads: rows y0..y0+R, cols [X, X+1] (float2) and X+2.
    float2 cdL[R + 1], dL[R + 1];
    float  cdR[R + 1], dR[R + 1];
#pragma unroll
    for (int i = 0; i <= R; i++) {
        int ry = y0 + i;
        ry = ry > H - 1 ? H - 1 : ry;  // clamp; clamped row's values unused
        int base = ry * W;
        cdL[i] = *reinterpret_cast<const float2*>(cp + base + X);
        dL[i]  = *reinterpret_cast<const float2*>(dp + base + X);
        cdR[i] = cp[base + x2];
        dR[i]  = dp[base + x2];
    }

    size_t N = (size_t)256 * OH * OW;
    bool alignedE = ((bc & 1) == 0);   // even output rows 8B-aligned
    bool alignedO = !alignedE;

#pragma unroll
    for (int r = 0; r < R; r++) {
        int y = y0 + r;
        bool ye = (y < H - 1);

        // block0: input cols (X, X+1)
        float dee0, deo0, doe0, doo0, cee0, ceo0, coe0, coo0;
        block2x2(cdL[r].x, cdL[r].y, cdL[r + 1].x, cdL[r + 1].y,
                 dL[r].x,  dL[r].y,  dL[r + 1].x,  dL[r + 1].y,
                 s0, s1, s2, s3, s4, s5, s6, s7, s8,
                 ree, reo, roe, roo, b,
                 dee0, deo0, doe0, doo0, cee0, ceo0, coe0, coo0);

        // block1: input cols (X+1, X+2)
        float dee1, deo1, doe1, doo1, cee1, ceo1, coe1, coo1;
        block2x2(cdL[r].y, cdR[r], cdL[r + 1].y, cdR[r + 1],
                 dL[r].y,  dR[r],  dL[r + 1].y,  dR[r + 1],
                 s0, s1, s2, s3, s4, s5, s6, s7, s8,
                 ree, reo, roe, roo, b,
                 dee1, deo1, doe1, doo1, cee1, ceo1, coe1, coo1);

        size_t rowE = ((size_t)bc * OH + 2 * y) * OW + 4 * (size_t)xt;
        float* pE = out + rowE;

        store_row4(pE,     dee0, deo0, dee1, deo1, alignedE, xe);
        store_row4(pE + N, cee0, ceo0, cee1, ceo1, alignedE, xe);

        if (ye) {
            float* pO = pE + OW;
            store_row4(pO,     doe0, doo0, doe1, doo1, alignedO, xe);
            store_row4(pO + N, coe0, coo0, coe1, coo1, alignedO, xe);
        }
    }
}

extern "C" void kernel_launch(void* const* d_in, const int* in_sizes, int n_in,
                              void* d_out, int out_size) {
    const float* d    = (const float*)d_in[0];
    const float* cd   = (const float*)d_in[1];
    const float* sw   = (const float*)d_in[2];
    const float* bias = (const float*)d_in[3];
    float* out = (float*)d_out;

    prep_kernel<<<1, 32>>>(sw, bias);

    dim3 block(64, 4);
    dim3 grid(2, 32, 256);  // x: 128 col-pairs / 64; y: 128 row-pairs / 4; z: B*C
    deconv_v4_kernel<<<grid, block>>>(d, cd, out);
}

// round 5
// speedup vs baseline: 2.4150x; 1.1136x over previous
#include <cuda_runtime.h>

// StructNDeconv2D: depthwise conv_transpose2d (K=3, stride=2, pad=1) normalized
// convolution. OH = 2H-1 = 511 so every tap is in bounds.
//
// Round-5: dense STG.128 stores via shifted row partitions.
// Output row oy has float base index bc*511^2 + oy*511, whose mod-4 residue is
// k=(bc+3*oy)&3. Shifting the per-row column partition by s=(oy-bc)&3 makes
// every 4-col chunk 16-byte aligned -> one STG.128 per chunk (fully dense
// per-instruction across the warp). A thread owns col-slot q and the 4 output
// rows 4*ry..4*ry+3; since 4*ry = 0 mod 4, the base shift SB = (-bc)&3 is
// uniform per block (template switch, no divergence). For any shift, the
// thread's input window is cols [2q, 2q+3] (two aligned float2 loads per row
// per array). Col-slot 127 handles the 3 leftover cols per row (head+tail).

#define EPS_F 1e-20f

struct Wts {
    float s0, s1, s2, s3, s4, s5, s6, s7, s8;
    float ree, reo, roe, roo, b;
};

// Per-channel packed params: [0..8]=softplus(w), [9..12]=1/(cden+eps) for
// ee/eo/oe/oo parity classes, [13]=bias. 64B aligned -> 4x LDG.128.
__device__ __align__(16) float g_wp[32][16];

__global__ void prep_kernel(const float* __restrict__ w,
                            const float* __restrict__ bias) {
    int c = threadIdx.x;
    if (c >= 32) return;
    float s[9];
#pragma unroll
    for (int i = 0; i < 9; i++) {
        float x = w[c * 9 + i];
        s[i] = fmaxf(x, 0.0f) + log1pf(expf(-fabsf(x)));  // softplus
        g_wp[c][i] = s[i];
    }
    g_wp[c][9]  = 1.0f / (s[4] + EPS_F);                      // ee
    g_wp[c][10] = 1.0f / (s[3] + s[5] + EPS_F);               // eo
    g_wp[c][11] = 1.0f / (s[1] + s[7] + EPS_F);               // oe
    g_wp[c][12] = 1.0f / (s[0] + s[2] + s[6] + s[8] + EPS_F); // oo
    g_wp[c][13] = bias[c];
    g_wp[c][14] = 0.0f;
    g_wp[c][15] = 0.0f;
}

// ---- per-pixel math -------------------------------------------------------
// Even output row, even col: center tap s4 @ input (y, ox/2).
__device__ __forceinline__ void pixE(float cv, float dv, const Wts& w,
                                     float& dd, float& cc) {
    float den = w.s4 * cv;
    dd = __fdividef(den * dv, den + EPS_F) + w.b;
    cc = den * w.ree;
}
// Even output row, odd col: s3 @ ixR=(ox+1)/2, s5 @ ixL=(ox-1)/2.
__device__ __forceinline__ void pixO(float cL, float dL, float cR, float dR,
                                     const Wts& w, float& dd, float& cc) {
    float a = w.s3 * cR, b2 = w.s5 * cL;
    float den = a + b2;
    dd = __fdividef(fmaf(a, dR, b2 * dL), den + EPS_F) + w.b;
    cc = den * w.reo;
}
// Odd output row, even col: s1 @ row y+1, s7 @ row y (col ox/2).
__device__ __forceinline__ void pixE2(float c0, float d0, float c1, float d1,
                                      const Wts& w, float& dd, float& cc) {
    float a = w.s1 * c1, b2 = w.s7 * c0;
    float den = a + b2;
    dd = __fdividef(fmaf(a, d1, b2 * d0), den + EPS_F) + w.b;
    cc = den * w.roe;
}
// Odd output row, odd col: s0@(y+1,ixR) s2@(y+1,ixL) s6@(y,ixR) s8@(y,ixL).
__device__ __forceinline__ void pixO2(float c0L, float d0L, float c0R, float d0R,
                                      float c1L, float d1L, float c1R, float d1R,
                                      const Wts& w, float& dd, float& cc) {
    float t0 = w.s0 * c1R, t2 = w.s2 * c1L, t6 = w.s6 * c0R, t8 = w.s8 * c0L;
    float den = (t0 + t2) + (t6 + t8);
    dd = __fdividef(fmaf(t0, d1R, fmaf(t2, d1L, fmaf(t6, d0R, t8 * d0L))),
                    den + EPS_F) + w.b;
    cc = den * w.roo;
}

// ---- 4-col chunks ---------------------------------------------------------
// Chunk covers output cols [S + 4q, S + 4q + 4); input window is cols
// [2q..2q+3] passed as cv[0..3]. Local tap indices derive from S at compile
// time: col parity pattern is [E,O,E,O] for even S, [O,E,O,E] for odd S.
template<int S>
__device__ __forceinline__ void even_chunk(const float* cv, const float* dv,
                                           const Wts& w, float* o, float* co) {
    constexpr int h = S >> 1;
    if constexpr ((S & 1) == 0) {
        pixE(cv[h],     dv[h],                         w, o[0], co[0]);
        pixO(cv[h],     dv[h],   cv[h+1], dv[h+1],     w, o[1], co[1]);
        pixE(cv[h+1],   dv[h+1],                       w, o[2], co[2]);
        pixO(cv[h+1],   dv[h+1], cv[h+2], dv[h+2],     w, o[3], co[3]);
    } else {
        pixO(cv[h],     dv[h],   cv[h+1], dv[h+1],     w, o[0], co[0]);
        pixE(cv[h+1],   dv[h+1],                       w, o[1], co[1]);
        pixO(cv[h+1],   dv[h+1], cv[h+2], dv[h+2],     w, o[2], co[2]);
        pixE(cv[h+2],   dv[h+2],                       w, o[3], co[3]);
    }
}

template<int S>
__device__ __forceinline__ void odd_chunk(const float* c0, const float* d0,
                                          const float* c1, const float* d1,
                                          const Wts& w, float* o, float* co) {
    constexpr int h = S >> 1;
    if constexpr ((S & 1) == 0) {
        pixE2(c0[h],   d0[h],   c1[h],   d1[h],   w, o[0], co[0]);
        pixO2(c0[h],   d0[h],   c0[h+1], d0[h+1],
              c1[h],   d1[h],   c1[h+1], d1[h+1], w, o[1], co[1]);
        pixE2(c0[h+1], d0[h+1], c1[h+1], d1[h+1], w, o[2], co[2]);
        pixO2(c0[h+1], d0[h+1], c0[h+2], d0[h+2],
              c1[h+1], d1[h+1], c1[h+2], d1[h+2], w, o[3], co[3]);
    } else {
        pixO2(c0[h],   d0[h],   c0[h+1], d0[h+1],
              c1[h],   d1[h],   c1[h+1], d1[h+1], w, o[0], co[0]);
        pixE2(c0[h+1], d0[h+1], c1[h+1], d1[h+1], w, o[1], co[1]);
        pixO2(c0[h+1], d0[h+1], c0[h+2], d0[h+2],
              c1[h+1], d1[h+1], c1[h+2], d1[h+2], w, o[2], co[2]);
        pixE2(c0[h+2], d0[h+2], c1[h+2], d1[h+2], w, o[3], co[3]);
    }
}

__device__ __forceinline__ void st4(float* p, const float* v) {
    __stcs(reinterpret_cast<float4*>(p), make_float4(v[0], v[1], v[2], v[3]));
}

// Process the thread's 4 output rows (oy = 4*ry + p, p=0..3).
// Input rows: cv[0]=y0, cv[1]=y0+1, cv[2]=y0+2 (y0 = 2*ry).
template<int SB>
__device__ __forceinline__ void doRows(const float cv[3][4], const float dv[3][4],
                                       const Wts& w, float* __restrict__ out,
                                       size_t N, size_t row0, int q, bool pm) {
    float o[4], co[4];
    size_t base = row0 + 4 * (size_t)q;

    even_chunk<SB>(cv[0], dv[0], w, o, co);
    st4(out + base + SB, o);
    st4(out + N + base + SB, co);

    odd_chunk<(SB + 1) & 3>(cv[0], dv[0], cv[1], dv[1], w, o, co);
    base += 511;
    st4(out + base + ((SB + 1) & 3), o);
    st4(out + N + base + ((SB + 1) & 3), co);

    even_chunk<(SB + 2) & 3>(cv[1], dv[1], w, o, co);
    base += 511;
    st4(out + base + ((SB + 2) & 3), o);
    st4(out + N + base + ((SB + 2) & 3), co);

    if (pm) {
        odd_chunk<(SB + 3) & 3>(cv[1], dv[1], cv[2], dv[2], w, o, co);
        base += 511;
        st4(out + base + ((SB + 3) & 3), o);
        st4(out + N + base + ((SB + 3) & 3), co);
    }
}

// Scalar pixel for the leftover columns (head/tail). Window is 2 cols wide
// starting at input col wb (0 or 254); all needed taps fall inside it.
__device__ __forceinline__ void edge_one(int ox, int wb, bool oddrow,
                                         const float* c0, const float* d0,
                                         const float* c1, const float* d1,
                                         const Wts& w, float* __restrict__ out,
                                         size_t N, size_t rowb) {
    float dd, cc;
    if ((ox & 1) == 0) {
        int li = (ox >> 1) - wb;
        float cva = li ? c0[1] : c0[0];
        float dva = li ? d0[1] : d0[0];
        if (!oddrow) {
            pixE(cva, dva, w, dd, cc);
        } else {
            float cvb = li ? c1[1] : c1[0];
            float dvb = li ? d1[1] : d1[0];
            pixE2(cva, dva, cvb, dvb, w, dd, cc);
        }
    } else {
        if (!oddrow) pixO(c0[0], d0[0], c0[1], d0[1], w, dd, cc);
        else         pixO2(c0[0], d0[0], c0[1], d0[1],
                           c1[0], d1[0], c1[1], d1[1], w, dd, cc);
    }
    __stcs(out + rowb + ox, dd);
    __stcs(out + N + rowb + ox, cc);
}

__global__ __launch_bounds__(256) void deconv_v5_kernel(
    const float* __restrict__ d,
    const float* __restrict__ cd,
    float* __restrict__ out)
{
    constexpr int W_ = 256, OH = 511, OW = 511;

    int q  = blockIdx.x * 64 + threadIdx.x;   // col slot [0,127]
    int ry = blockIdx.y * 4 + threadIdx.y;    // row-pair group [0,127]
    int y0 = ry * 2;                          // first input row
    int bc = blockIdx.z;
    int c  = bc & 31;

    Wts w;
    {
        const float4* wp = reinterpret_cast<const float4*>(g_wp[c]);
        float4 a = wp[0], b4 = wp[1], c4 = wp[2], d4 = wp[3];
        w.s0 = a.x;  w.s1 = a.y;  w.s2 = a.z;  w.s3 = a.w;
        w.s4 = b4.x; w.s5 = b4.y; w.s6 = b4.z; w.s7 = b4.w;
        w.s8 = c4.x; w.ree = c4.y; w.reo = c4.z; w.roe = c4.w;
        w.roo = d4.x; w.b = d4.y;
    }

    int SB = (-bc) & 3;                        // shift of row oy=4*ry
    size_t plane = (size_t)bc * (W_ * W_);
    const float* cp = cd + plane;
    const float* dp = d + plane;
    size_t N = (size_t)256 * OH * OW;
    bool pm = (ry != 127);                     // output row 4*ry+3 exists

    if (q < 127) {
        int X = 2 * q;
        float cv[3][4], dv[3][4];
#pragma unroll
        for (int i = 0; i < 3; i++) {
            int ryi = y0 + i; if (ryi > 255) ryi = 255;  // clamped row unused
            const float* cr = cp + ryi * W_ + X;
            const float* dr = dp + ryi * W_ + X;
            float2 a = *reinterpret_cast<const float2*>(cr);
            float2 b2 = *reinterpret_cast<const float2*>(cr + 2);
            float2 e = *reinterpret_cast<const float2*>(dr);
            float2 f = *reinterpret_cast<const float2*>(dr + 2);
            cv[i][0] = a.x; cv[i][1] = a.y; cv[i][2] = b2.x; cv[i][3] = b2.y;
            dv[i][0] = e.x; dv[i][1] = e.y; dv[i][2] = f.x;  dv[i][3] = f.y;
        }
        size_t row0 = ((size_t)bc * OH + 4 * (size_t)ry) * OW;
        switch (SB) {
            case 0: doRows<0>(cv, dv, w, out, N, row0, q, pm); break;
            case 1: doRows<1>(cv, dv, w, out, N, row0, q, pm); break;
            case 2: doRows<2>(cv, dv, w, out, N, row0, q, pm); break;
            default: doRows<3>(cv, dv, w, out, N, row0, q, pm); break;
        }
    } else {
        // Leftover columns: head [0, S) and tail [S+508, 511) per row.
        float chh[3][2], dhh[3][2], ctt[3][2], dtt[3][2];
#pragma unroll
        for (int i = 0; i < 3; i++) {
            int ryi = y0 + i; if (ryi > 255) ryi = 255;
            const float* crow = cp + ryi * W_;
            const float* drow = dp + ryi * W_;
            float2 a = *reinterpret_cast<const float2*>(crow);
            float2 b2 = *reinterpret_cast<const float2*>(crow + 254);
            float2 e = *reinterpret_cast<const float2*>(drow);
            float2 f = *reinterpret_cast<const float2*>(drow + 254);
            chh[i][0] = a.x; chh[i][1] = a.y; ctt[i][0] = b2.x; ctt[i][1] = b2.y;
            dhh[i][0] = e.x; dhh[i][1] = e.y; dtt[i][0] = f.x;  dtt[i][1] = f.y;
        }
#pragma unroll
        for (int p = 0; p < 4; p++) {
            if (p == 3 && !pm) break;
            int S = (SB + p) & 3;
            int oy = 4 * ry + p;
            size_t rowb = ((size_t)bc * OH + oy) * OW;
            int r0 = (p <= 1) ? 0 : 1;    // lower input row index
            bool oddrow = (p & 1);
            for (int ox = 0; ox < S; ox++)
                edge_one(ox, 0, oddrow, chh[r0], dhh[r0],
                         chh[r0 + 1], dhh[r0 + 1], w, out, N, rowb);
            for (int ox = S + 508; ox < 511; ox++)
                edge_one(ox, 254, oddrow, ctt[r0], dtt[r0],
                         ctt[r0 + 1], dtt[r0 + 1], w, out, N, rowb);
        }
    }
}

extern "C" void kernel_launch(void* const* d_in, const int* in_sizes, int n_in,
                              void* d_out, int out_size) {
    const float* d    = (const float*)d_in[0];
    const float* cd   = (const float*)d_in[1];
    const float* sw   = (const float*)d_in[2];
    const float* bias = (const float*)d_in[3];
    float* out = (float*)d_out;

    prep_kernel<<<1, 32>>>(sw, bias);

    dim3 block(64, 4);
    dim3 grid(2, 32, 256);  // x: 128 col slots / 64; y: 128 row groups / 4; z: B*C
    deconv_v5_kernel<<<grid, block>>>(d, cd, out);
}